// round 17
// baseline (speedup 1.0000x reference)
#include <cuda_runtime.h>

#define N_IMG 8
#define H 32
#define W 32
#define CIN 32
#define COUT 64
#define HO 30
#define WO 30
#define PDIM (3*3*CIN)           // 288

typedef unsigned long long u64;
typedef unsigned int u32;

// ---------------------------------------------------------------------------
// g_wp2: packed weight pairs, item = (half*288 + k)*16 + pr :
//   ulonglong2 { f32x2{ek1[k][c0],ek1[k][c0+1]}, f32x2{ek2[k][c0],ek2[k][c0+1]} }
//   c0 = half*32 + pr*2
// ---------------------------------------------------------------------------
__device__ __align__(16) ulonglong2 g_wp2[2*PDIM*16];   // 9216 entries, 147KB

#define SW_BYTES   (PDIM*16*16)          // 73728 per half
#define SV_PLANE   (3*32*34)             // 3264 floats per sign plane
#define SMEM_BYTES (SW_BYTES + 2*SV_PLANE*4)   // 99840

// Two packed f32x2 multiplies, fold both into each u32 acc with one 3-input
// DPX max. Valid: all products strictly positive finite (v>=0.1, w=exp(k)>0);
// positive IEEE floats order like u32.
__device__ __forceinline__ void mm3(u64 v0, u64 w0, u64 v1, u64 w1,
                                    u32& a0, u32& a1) {
    u32 p0lo, p0hi, p1lo, p1hi;
    asm("{\n\t"
        ".reg .b64 t0, t1;\n\t"
        "mul.rn.f32x2 t0, %4, %5;\n\t"
        "mul.rn.f32x2 t1, %6, %7;\n\t"
        "mov.b64 {%0, %1}, t0;\n\t"
        "mov.b64 {%2, %3}, t1;\n\t"
        "}"
        : "=r"(p0lo), "=r"(p0hi), "=r"(p1lo), "=r"(p1hi)
        : "l"(v0), "l"(w0), "l"(v1), "l"(w1));
    a0 = __vimax3_u32(a0, p0lo, p1lo);
    a1 = __vimax3_u32(a1, p0hi, p1hi);
}

// One packed multiply, scalar max fold.
__device__ __forceinline__ void mulmax1(u64 v, u64 w, u32& a0, u32& a1) {
    u32 plo, phi;
    asm("{\n\t"
        ".reg .b64 t;\n\t"
        "mul.rn.f32x2 t, %2, %3;\n\t"
        "mov.b64 {%0, %1}, t;\n\t"
        "}" : "=r"(plo), "=r"(phi) : "l"(v), "l"(w));
    a0 = umax(a0, plo);
    a1 = umax(a1, phi);
}

__device__ __forceinline__ u64 pack2(float lo, float hi) {
    u64 d; asm("mov.b64 %0, {%1, %2};" : "=l"(d) : "f"(lo), "f"(hi)); return d;
}
__device__ __forceinline__ u64 splat2(float v) {
    u64 d; asm("mov.b64 %0, {%1, %1};" : "=l"(d) : "f"(v)); return d;
}
__device__ __forceinline__ float2 f2u(u64 v) {
    float2 r; asm("mov.b64 {%0, %1}, %2;" : "=f"(r.x), "=f"(r.y) : "l"(v));
    return r;
}
__device__ __forceinline__ u64 packh(float lo, float hi) {
    return (u64)__float_as_uint(lo) | ((u64)__float_as_uint(hi) << 32);
}

// ---------------------------------------------------------------------------
// Prep: weights only (v now staged straight from x inside morph).
// ---------------------------------------------------------------------------
__global__ void prep(const float* __restrict__ k1, const float* __restrict__ k2) {
    const int item = blockIdx.x*256 + threadIdx.x;
    if (item < 2*PDIM*16) {
        const int half = item / (PDIM*16);
        const int rem  = item - half*(PDIM*16);
        const int k    = rem >> 4;
        const int pr   = rem & 15;
        const int base = k*COUT + half*32 + pr*2;
        ulonglong2 e;
        e.x = packh(expf(k1[base]), expf(k1[base+1]));
        e.y = packh(expf(k2[base]), expf(k2[base+1]));
        g_wp2[item] = e;
    }
}

// ---------------------------------------------------------------------------
// Main: CTA = 512 thr = 16 warps; blockIdx = (row 0..239) x (cout-half 0..1).
// Warp wid: wcg = wid&7 (cout-pair group), cih = wid>>3 (ci half, 16 ci).
// Lane: pxp = l&15 (pixel pair 2pxp,2pxp+1), cgbit = l>>4; pr = wcg*2+cgbit.
// Each lane: 2 pixels x 2 couts x 4 tables = 16 u32 accs, pixels packed in
// the f32x2 lanes. v loads shared across all 3 j positions (j1 via 1 pack).
// Crossbar: 80B per (i,ci) per lane for 48 products = 1.67 B/product
// (R13: 2.5) -- the measured binder.
// 2-way ci combine through the (dead) weight smem region.
// ---------------------------------------------------------------------------
__global__ void __launch_bounds__(512, 2)
morph_main(const float* __restrict__ x, const float* __restrict__ bias,
           float* __restrict__ out) {
    extern __shared__ __align__(16) char smem[];
    ulonglong2* s_w  = reinterpret_cast<ulonglong2*>(smem);
    float*      s_vp = reinterpret_cast<float*>(smem + SW_BYTES);
    float*      s_vn = s_vp + SV_PLANE;
    u32*        s_r  = reinterpret_cast<u32*>(smem);   // reused after loop

    const int tid   = threadIdx.x;
    const int wid   = tid >> 5;
    const int lane  = tid & 31;
    const int wcg   = wid & 7;
    const int cih   = wid >> 3;
    const int pxp   = lane & 15;
    const int cgbit = lane >> 4;
    const int pr    = wcg*2 + cgbit;   // cout pair 0..15
    const int row   = blockIdx.x >> 1;
    const int half  = blockIdx.x & 1;
    const int n     = row / HO;
    const int ho    = row - n*HO;
    const int c0    = half*32 + pr*2;

    // Stage weights for this cout-half (contiguous 73728B)
    {
        const ulonglong2* __restrict__ src = g_wp2 + half*(PDIM*16);
        for (int idx = tid; idx < PDIM*16; idx += 512)
            s_w[idx] = src[idx];
    }
    // Stage v planes straight from x (rows ho..ho+2), clamp both signs.
    for (int idx = tid; idx < 3*32*32; idx += 512) {
        const int i  = idx >> 10;
        const int w  = (idx >> 5) & 31;
        const int ci = idx & 31;
        const float val = x[((n*H + ho + i)*W + w)*CIN + ci];
        const int o = (i*32 + ci)*34 + w;
        s_vp[o] = fmaxf(val, 0.1f);
        s_vn[o] = fmaxf(-val, 0.1f);
    }
    __syncthreads();

    // m[t: 11,12,21,22][cout 0..1][px half 0..1]
    u32 m[4][2][2];
    #pragma unroll
    for (int t = 0; t < 4; t++)
        #pragma unroll
        for (int c = 0; c < 2; c++) { m[t][c][0] = 0u; m[t][c][1] = 0u; }

    #pragma unroll 1
    for (int i = 0; i < 3; i++) {
        const float* vp = s_vp + (i*32 + cih*16)*34 + 2*pxp;
        const float* vn = s_vn + (i*32 + cih*16)*34 + 2*pxp;
        const ulonglong2* wr = s_w + (i*96 + cih*16)*16 + pr;

        #pragma unroll 2
        for (int cc = 0; cc < 16; cc++) {
            const float2 a  = *reinterpret_cast<const float2*>(vp);
            const float2 b  = *reinterpret_cast<const float2*>(vp + 2);
            const float2 cf = *reinterpret_cast<const float2*>(vn);
            const float2 d  = *reinterpret_cast<const float2*>(vn + 2);
            const u64 Vp0 = pack2(a.x, a.y);    // j=0 pair (elided alias)
            const u64 Vp1 = pack2(a.y, b.x);    // j=1 pair (1 MOV)
            const u64 Vp2 = pack2(b.x, b.y);    // j=2 pair (elided alias)
            const u64 Vn0 = pack2(cf.x, cf.y);
            const u64 Vn1 = pack2(cf.y, d.x);
            const u64 Vn2 = pack2(d.x, d.y);
            const ulonglong2 W0 = wr[0];        // k = (i*3+0)*32 + ci
            const ulonglong2 W1 = wr[512];      // j=1
            const ulonglong2 W2 = wr[1024];     // j=2

            #pragma unroll
            for (int tb = 0; tb < 2; tb++) {
                const float2 f0 = f2u(tb ? W0.y : W0.x);
                const float2 f1 = f2u(tb ? W1.y : W1.x);
                const float2 g2 = f2u(tb ? W2.y : W2.x);
                #pragma unroll
                for (int c = 0; c < 2; c++) {
                    const u64 s0 = splat2(c ? f0.y : f0.x);
                    const u64 s1 = splat2(c ? f1.y : f1.x);
                    const u64 s2 = splat2(c ? g2.y : g2.x);
                    mm3(Vp0, s0, Vp1, s1, m[tb][c][0], m[tb][c][1]);
                    mulmax1(Vp2, s2,      m[tb][c][0], m[tb][c][1]);
                    mm3(Vn0, s0, Vn1, s1, m[2+tb][c][0], m[2+tb][c][1]);
                    mulmax1(Vn2, s2,      m[2+tb][c][0], m[2+tb][c][1]);
                }
            }
            vp += 34; vn += 34; wr += 16;
        }
    }

    // 2-way ci-half combine in the (dead) weight smem region.
    __syncthreads();
    if (cih == 1) {
        u32* dst = s_r + (wcg*32 + lane)*16;
        #pragma unroll
        for (int t = 0; t < 4; t++)
            #pragma unroll
            for (int c = 0; c < 2; c++) {
                dst[(t*2 + c)*2]     = m[t][c][0];
                dst[(t*2 + c)*2 + 1] = m[t][c][1];
            }
    }
    __syncthreads();
    if (cih == 0 && pxp < 15) {
        const u32* src = s_r + (wcg*32 + lane)*16;
        #pragma unroll
        for (int t = 0; t < 4; t++)
            #pragma unroll
            for (int c = 0; c < 2; c++) {
                m[t][c][0] = umax(m[t][c][0], src[(t*2 + c)*2]);
                m[t][c][1] = umax(m[t][c][1], src[(t*2 + c)*2 + 1]);
            }

        const float2 bv = *reinterpret_cast<const float2*>(bias + c0);
        const int qb = (n*HO + ho)*WO + 2*pxp;
        #pragma unroll
        for (int h = 0; h < 2; h++) {
            float2 r;
            r.x = __uint_as_float(m[0][0][h]) - __uint_as_float(m[1][0][h])
                - __uint_as_float(m[2][0][h]) + __uint_as_float(m[3][0][h]) + bv.x;
            r.y = __uint_as_float(m[0][1][h]) - __uint_as_float(m[1][1][h])
                - __uint_as_float(m[2][1][h]) + __uint_as_float(m[3][1][h]) + bv.y;
            *reinterpret_cast<float2*>(out + (size_t)(qb + h)*COUT + c0) = r;
        }
    }
}

// ---------------------------------------------------------------------------
extern "C" void kernel_launch(void* const* d_in, const int* in_sizes, int n_in,
                              void* d_out, int out_size) {
    const float* x    = (const float*)d_in[0];
    const float* k1   = (const float*)d_in[1];
    const float* k2   = (const float*)d_in[2];
    const float* bias = (const float*)d_in[3];
    float* out = (float*)d_out;

    cudaFuncSetAttribute(morph_main,
                         cudaFuncAttributeMaxDynamicSharedMemorySize,
                         SMEM_BYTES);

    prep<<<(2*PDIM*16 + 255)/256, 256>>>(k1, k2);
    morph_main<<<240*2, 512, SMEM_BYTES>>>(x, bias, out);
}